// round 2
// baseline (speedup 1.0000x reference)
#include <cuda_runtime.h>
#include <math.h>

#define NPTS 262144
#define CH   256
#define NB   8
#define ROWS 16
#define MCHUNK 32
#define EPSV 1e-5f

// scratch (no allocations allowed; __device__ globals are the sanctioned path)
__device__ int   g_off[NB + 1];
__device__ float g_part[NB * MCHUNK][3];

// ---------------------------------------------------------------- k_prep
// lengths dtype is ambiguous (jax silently downgrades int64->int32 unless x64
// is enabled). Sniff it: read as int32 first (32B, safe under either dtype);
// if the sum matches NPTS it's int32, else re-read as int64.
__global__ void k_prep(const void* __restrict__ lengths_raw) {
    if (threadIdx.x == 0) {
        const int*       l32 = (const int*)lengths_raw;
        long long v[NB];
        long long s32 = 0;
        for (int i = 0; i < NB; i++) s32 += l32[i];
        if (s32 == (long long)NPTS) {
            for (int i = 0; i < NB; i++) v[i] = l32[i];
        } else {
            const long long* l64 = (const long long*)lengths_raw;
            for (int i = 0; i < NB; i++) v[i] = l64[i];
        }
        long long acc = 0;
        g_off[0] = 0;
        for (int i = 0; i < NB; i++) {
            acc += v[i];
            long long c = acc < 0 ? 0 : (acc > NPTS ? NPTS : acc);  // never OOB
            g_off[i + 1] = (int)c;
        }
        g_off[NB] = NPTS;
    }
}

// ---------------------------------------------------------------- k_means (partials, deterministic)
__global__ void k_means(const float* __restrict__ coord) {
    const int b = blockIdx.x / MCHUNK;
    const int chunk = blockIdx.x % MCHUNK;
    const int s = g_off[b], e = g_off[b + 1];
    const int len = e - s;
    const int cs = s + (int)(((long long)len * chunk) / MCHUNK);
    const int ce = s + (int)(((long long)len * (chunk + 1)) / MCHUNK);

    float sx = 0.f, sy = 0.f, sz = 0.f;
    for (int i = cs + threadIdx.x; i < ce; i += 256) {
        sx += coord[(size_t)i * 3 + 0];
        sy += coord[(size_t)i * 3 + 1];
        sz += coord[(size_t)i * 3 + 2];
    }
#pragma unroll
    for (int o = 16; o > 0; o >>= 1) {
        sx += __shfl_xor_sync(0xffffffffu, sx, o);
        sy += __shfl_xor_sync(0xffffffffu, sy, o);
        sz += __shfl_xor_sync(0xffffffffu, sz, o);
    }
    __shared__ float red[8][3];
    const int lane = threadIdx.x & 31, w = threadIdx.x >> 5;
    if (lane == 0) { red[w][0] = sx; red[w][1] = sy; red[w][2] = sz; }
    __syncthreads();
    if (threadIdx.x < 3) {
        float a = 0.f;
#pragma unroll
        for (int i = 0; i < 8; i++) a += red[i][threadIdx.x];
        g_part[blockIdx.x][threadIdx.x] = a;
    }
}

// ---------------------------------------------------------------- k_main
__global__ void __launch_bounds__(256) k_main(
    const float* __restrict__ feat, const float* __restrict__ coord,
    const float* __restrict__ w_xyz, const float* __restrict__ b_xyz,
    const float* __restrict__ g1, const float* __restrict__ be1,
    const float* __restrict__ w_conv, const float* __restrict__ b_conv,
    const float* __restrict__ g2, const float* __restrict__ be2,
    float* __restrict__ out)
{
    __shared__ float sf[ROWS + 2][CH];
    __shared__ int   s_off[NB + 1];
    __shared__ float s_mean[NB][3];

    const int tid  = threadIdx.x;
    const int lane = tid & 31;
    const int warp = tid >> 5;
    const int cb   = lane * 8;            // 8 channels per lane, c = cb..cb+7
    const int r0   = blockIdx.x * ROWS;

    if (tid <= NB) s_off[tid] = g_off[tid];
    if (tid >= 32 && tid < 32 + NB * 3) {
        const int b = (tid - 32) / 3, d = (tid - 32) % 3;
        float a = 0.f;
#pragma unroll
        for (int i = 0; i < MCHUNK; i++) a += g_part[b * MCHUNK + i][d];
        const int len = g_off[b + 1] - g_off[b];
        s_mean[b][d] = a / (float)(len > 0 ? len : 1);
    }
    __syncthreads();

    // ---- phase-1 params (registers, per-lane channel slice)
    float wx[8], wy[8], wz[8], bx[8], ga[8], bb[8];
    *(float4*)&wx[0] = *(const float4*)&w_xyz[0 * CH + cb];
    *(float4*)&wx[4] = *(const float4*)&w_xyz[0 * CH + cb + 4];
    *(float4*)&wy[0] = *(const float4*)&w_xyz[1 * CH + cb];
    *(float4*)&wy[4] = *(const float4*)&w_xyz[1 * CH + cb + 4];
    *(float4*)&wz[0] = *(const float4*)&w_xyz[2 * CH + cb];
    *(float4*)&wz[4] = *(const float4*)&w_xyz[2 * CH + cb + 4];
    *(float4*)&bx[0] = *(const float4*)&b_xyz[cb];
    *(float4*)&bx[4] = *(const float4*)&b_xyz[cb + 4];
    *(float4*)&ga[0] = *(const float4*)&g1[cb];
    *(float4*)&ga[4] = *(const float4*)&g1[cb + 4];
    *(float4*)&bb[0] = *(const float4*)&be1[cb];
    *(float4*)&bb[4] = *(const float4*)&be1[cb + 4];

    // ---- phase 1: f = feat + gelu(LN(xyz_c @ W + b)) for rows r0-1 .. r0+ROWS
    for (int j = warp; j < ROWS + 2; j += 8) {
        const int gr = r0 - 1 + j;
        if (gr < 0 || gr >= NPTS) continue;   // warp-uniform branch

        int seg = 0;
#pragma unroll
        for (int b = 1; b < NB; b++) seg += (gr >= s_off[b]);
        const float xc = coord[(size_t)3 * gr + 0] - s_mean[seg][0];
        const float yc = coord[(size_t)3 * gr + 1] - s_mean[seg][1];
        const float zc = coord[(size_t)3 * gr + 2] - s_mean[seg][2];

        float z[8]; float s = 0.f, s2 = 0.f;
#pragma unroll
        for (int k = 0; k < 8; k++) {
            const float v = fmaf(xc, wx[k], fmaf(yc, wy[k], fmaf(zc, wz[k], bx[k])));
            z[k] = v; s += v; s2 += v * v;
        }
#pragma unroll
        for (int o = 16; o > 0; o >>= 1) {
            s  += __shfl_xor_sync(0xffffffffu, s,  o);
            s2 += __shfl_xor_sync(0xffffffffu, s2, o);
        }
        const float mu   = s * (1.f / CH);
        const float rstd = rsqrtf(fmaf(-mu, mu, s2 * (1.f / CH)) + EPSV);

        const float4 fa = *(const float4*)&feat[(size_t)gr * CH + cb];
        const float4 fb = *(const float4*)&feat[(size_t)gr * CH + cb + 4];
        const float fv[8] = {fa.x, fa.y, fa.z, fa.w, fb.x, fb.y, fb.z, fb.w};

        float o8[8];
#pragma unroll
        for (int k = 0; k < 8; k++) {
            const float t = fmaf((z[k] - mu) * rstd, ga[k], bb[k]);
            const float p = 0.5f * t * (1.f + erff(t * 0.70710678118654752f));
            o8[k] = fv[k] + p;
        }
        *(float4*)&sf[j][cb]     = make_float4(o8[0], o8[1], o8[2], o8[3]);
        *(float4*)&sf[j][cb + 4] = make_float4(o8[4], o8[5], o8[6], o8[7]);
    }
    __syncthreads();

    // ---- phase-2 params
    float wc0[8], wc1[8], wc2[8], bc[8], g2v[8], be2v[8];
#pragma unroll
    for (int k = 0; k < 8; k++) {
        wc0[k] = w_conv[(cb + k) * 3 + 0];
        wc1[k] = w_conv[(cb + k) * 3 + 1];
        wc2[k] = w_conv[(cb + k) * 3 + 2];
    }
    *(float4*)&bc[0]   = *(const float4*)&b_conv[cb];
    *(float4*)&bc[4]   = *(const float4*)&b_conv[cb + 4];
    *(float4*)&g2v[0]  = *(const float4*)&g2[cb];
    *(float4*)&g2v[4]  = *(const float4*)&g2[cb + 4];
    *(float4*)&be2v[0] = *(const float4*)&be2[cb];
    *(float4*)&be2v[4] = *(const float4*)&be2[cb + 4];

    // ---- phase 2: out = LN(feat + depthwise_conv(f))
    for (int j = warp; j < ROWS; j += 8) {
        const int n = r0 + j;
        int seg = 0;
#pragma unroll
        for (int b = 1; b < NB; b++) seg += (n >= s_off[b]);
        const bool pok = (n - 1) >= s_off[seg];
        const bool nok = (n + 1) <  s_off[seg + 1];

        const float4 fa = *(const float4*)&feat[(size_t)n * CH + cb];
        const float4 fb = *(const float4*)&feat[(size_t)n * CH + cb + 4];
        const float fv[8] = {fa.x, fa.y, fa.z, fa.w, fb.x, fb.y, fb.z, fb.w};

        float y[8]; float s = 0.f, s2 = 0.f;
#pragma unroll
        for (int k = 0; k < 8; k++) {
            const float fp = pok ? sf[j][cb + k]     : 0.f;   // select, not multiply (halo may be garbage)
            const float fc =       sf[j + 1][cb + k];
            const float fn = nok ? sf[j + 2][cb + k] : 0.f;
            const float conv = fmaf(fp, wc0[k], fmaf(fc, wc1[k], fmaf(fn, wc2[k], bc[k])));
            const float v = fv[k] + conv;
            y[k] = v; s += v; s2 += v * v;
        }
#pragma unroll
        for (int o = 16; o > 0; o >>= 1) {
            s  += __shfl_xor_sync(0xffffffffu, s,  o);
            s2 += __shfl_xor_sync(0xffffffffu, s2, o);
        }
        const float mu   = s * (1.f / CH);
        const float rstd = rsqrtf(fmaf(-mu, mu, s2 * (1.f / CH)) + EPSV);

        float o8[8];
#pragma unroll
        for (int k = 0; k < 8; k++)
            o8[k] = fmaf((y[k] - mu) * rstd, g2v[k], be2v[k]);

        *(float4*)&out[(size_t)n * CH + cb]     = make_float4(o8[0], o8[1], o8[2], o8[3]);
        *(float4*)&out[(size_t)n * CH + cb + 4] = make_float4(o8[4], o8[5], o8[6], o8[7]);
    }
}

// ---------------------------------------------------------------- launch
extern "C" void kernel_launch(void* const* d_in, const int* in_sizes, int n_in,
                              void* d_out, int out_size) {
    const float* feat    = (const float*)d_in[0];
    const float* coord   = (const float*)d_in[1];
    const void*  lengths = d_in[2];
    const float* w_xyz   = (const float*)d_in[3];
    const float* b_xyz   = (const float*)d_in[4];
    const float* g1v     = (const float*)d_in[5];
    const float* be1     = (const float*)d_in[6];
    const float* w_conv  = (const float*)d_in[7];
    const float* b_conv  = (const float*)d_in[8];
    const float* g2vv    = (const float*)d_in[9];
    const float* be2     = (const float*)d_in[10];
    float* out = (float*)d_out;

    k_prep<<<1, 32>>>(lengths);
    k_means<<<NB * MCHUNK, 256>>>(coord);
    k_main<<<NPTS / ROWS, 256>>>(feat, coord, w_xyz, b_xyz, g1v, be1,
                                 w_conv, b_conv, g2vv, be2, out);
}